// round 14
// baseline (speedup 1.0000x reference)
#include <cuda_runtime.h>

// Problem constants
#define T_STEPS 100
#define BATCH   256
#define N_IN    1024
#define N_HID   4096
#define N_OUT   512
#define KHALF   512            // gemm1 split-K=2 boundary (validated R9)
#define NCHUNK  10             // t-chunks for gemm1/step overlap
#define TCHUNK  (T_STEPS / NCHUNK)

#define BETA   0.95f
#define THRESH 1.0f

typedef unsigned long long ull;

// Packed fp32x2: each lane is an independent IEEE fp32 RN FMA -> packed
// accumulators hold two independent scalar fmaf chains, bitwise identical.
__device__ __forceinline__ ull dup2(float x) {
    ull r; asm("mov.b64 %0, {%1, %1};" : "=l"(r) : "f"(x)); return r;
}
__device__ __forceinline__ void ffma2(ull& acc, ull a, ull b) {
    asm("fma.rn.f32x2 %0, %1, %2, %0;" : "+l"(acc) : "l"(a), "l"(b));
}
__device__ __forceinline__ float2 unpk(ull v) {
    float2 f; asm("mov.b64 {%0, %1}, %2;" : "=f"(f.x), "=f"(f.y) : "l"(v)); return f;
}

// ---------------------------------------------------------------------------
// RULE: __device__ globals are referenced ONLY inside device code.
// ---------------------------------------------------------------------------
__device__ float g_cur1[(size_t)T_STEPS * BATCH * N_HID];   // 419 MB
__device__ float g_p0  [(size_t)T_STEPS * BATCH * N_HID];   // 419 MB split-K p0
__device__ float g_mem1[BATCH * N_HID];
__device__ float g_mem2[BATCH * N_OUT];
__device__ float g_W2T[(size_t)N_HID * N_OUT];              // 8 MB transposed W2

__global__ void init_kernel() {
    int i = blockIdx.x * blockDim.x + threadIdx.x;
    if (i < BATCH * N_HID) g_mem1[i] = 0.0f;
    if (i < BATCH * N_OUT) g_mem2[i] = 0.0f;
}

// ---------------------------------------------------------------------------
// One-time transpose: g_W2T[k][n] = W2[n][k].
// ---------------------------------------------------------------------------
__global__ __launch_bounds__(256) void transpose_w2_kernel(const float* __restrict__ W2) {
    __shared__ float tile[32][33];
    const int k0 = blockIdx.x * 32;
    const int n0 = blockIdx.y * 32;
    const int tx = threadIdx.x & 31;
    const int ty = threadIdx.x >> 5;
    #pragma unroll
    for (int i = 0; i < 4; i++)
        tile[ty + i * 8][tx] = W2[(size_t)(n0 + ty + i * 8) * N_HID + k0 + tx];
    __syncthreads();
    #pragma unroll
    for (int i = 0; i < 4; i++)
        g_W2T[(size_t)(k0 + ty + i * 8) * N_OUT + n0 + tx] = tile[tx][ty + i * 8];
}

// ---------------------------------------------------------------------------
// GEMM1 v3: one k-half per launch. 256x128 block tile, BK=16, 256 threads,
// 16m x 8n per thread (8 packed m-pair accumulators x 8 n).
// half=0: acc = chain(k 0..511), write p0.
// half=1: acc = chain(k 512..1023), out = ((p0 + acc) + bias) -> g_cur1.
// Per-output arithmetic identical to R9's validated (p0+p1)+b1.
//
// A smem row (256 m, padded 260): m = 16*tm + 4*c + q stored at c*64 + 4*tm + q
//   -> thread tm reads 4 contiguous 16B chunks (broadcast across warp).
// B smem row (128 n, padded 132): n = 8*tn + (q | chunk*4) at existing g1_off.
// ---------------------------------------------------------------------------
#define G1_BK   16
#define G1_AROW 260
#define G1_BROW 132

__device__ __forceinline__ int off_a(int x) {   // x = m index 0..255
    return ((x & 12) >> 2) * 64 + ((x >> 4) << 2) + (x & 3);
}
__device__ __forceinline__ int off_b(int x) {   // x = n index 0..127
    return ((x & 4) << 4) + ((x >> 3) << 2) + (x & 3);
}

__global__ __launch_bounds__(256, 1) void gemm1_half_kernel(
    const float* __restrict__ A,     // [25600, N_IN]
    const float* __restrict__ W,     // [N_HID, N_IN]
    const float* __restrict__ bias,  // [N_HID]
    int m_base, int half)
{
    __shared__ float As[G1_BK * G1_AROW];
    __shared__ float Bs[G1_BK * G1_BROW];

    const int tid = threadIdx.x;
    const int m0 = m_base + blockIdx.y * 256;
    const int n0 = blockIdx.x * 128;
    const int tm = tid >> 4;          // 0..15 -> m rows m0+16*tm .. +15
    const int tn = tid & 15;          // 0..15 -> n cols n0+8*tn .. +7

    const int kbeg = half ? KHALF : 0;

    ull acc[8][8];                    // [m-pair][n]
    #pragma unroll
    for (int p = 0; p < 8; p++)
        #pragma unroll
        for (int n = 0; n < 8; n++) acc[p][n] = 0ULL;

    // Loader coords: A 4 float4/thread, B 2 float4/thread per tile
    int arr[4], akv[4], brr[2], bkv[2];
    #pragma unroll
    for (int i = 0; i < 4; i++) {
        int l = tid + (i << 8);
        arr[i] = l >> 2; akv[i] = (l & 3) << 2;
    }
    #pragma unroll
    for (int i = 0; i < 2; i++) {
        int l = tid + (i << 8);
        brr[i] = l >> 2; bkv[i] = (l & 3) << 2;
    }

    float4 pa[4], pb[2];
    #pragma unroll
    for (int i = 0; i < 4; i++)
        pa[i] = *(const float4*)(A + (size_t)(m0 + arr[i]) * N_IN + kbeg + akv[i]);
    #pragma unroll
    for (int i = 0; i < 2; i++)
        pb[i] = *(const float4*)(W + (size_t)(n0 + brr[i]) * N_IN + kbeg + bkv[i]);

    for (int k0 = kbeg; k0 < kbeg + KHALF; k0 += G1_BK) {
        #pragma unroll
        for (int i = 0; i < 4; i++) {
            int o = off_a(arr[i]);
            As[(akv[i] + 0) * G1_AROW + o] = pa[i].x;
            As[(akv[i] + 1) * G1_AROW + o] = pa[i].y;
            As[(akv[i] + 2) * G1_AROW + o] = pa[i].z;
            As[(akv[i] + 3) * G1_AROW + o] = pa[i].w;
        }
        #pragma unroll
        for (int i = 0; i < 2; i++) {
            int o = off_b(brr[i]);
            Bs[(bkv[i] + 0) * G1_BROW + o] = pb[i].x;
            Bs[(bkv[i] + 1) * G1_BROW + o] = pb[i].y;
            Bs[(bkv[i] + 2) * G1_BROW + o] = pb[i].z;
            Bs[(bkv[i] + 3) * G1_BROW + o] = pb[i].w;
        }
        __syncthreads();

        if (k0 + G1_BK < kbeg + KHALF) {
            #pragma unroll
            for (int i = 0; i < 4; i++)
                pa[i] = *(const float4*)(A + (size_t)(m0 + arr[i]) * N_IN + k0 + G1_BK + akv[i]);
            #pragma unroll
            for (int i = 0; i < 2; i++)
                pb[i] = *(const float4*)(W + (size_t)(n0 + brr[i]) * N_IN + k0 + G1_BK + bkv[i]);
        }

        #pragma unroll
        for (int kk = 0; kk < G1_BK; kk++) {
            const float* ak = As + kk * G1_AROW;
            const float* bk = Bs + kk * G1_BROW;
            ulonglong2 A0 = *(const ulonglong2*)(ak + 4 * tm);          // pairs 0,1
            ulonglong2 A1 = *(const ulonglong2*)(ak + 64 + 4 * tm);     // pairs 2,3
            ulonglong2 A2 = *(const ulonglong2*)(ak + 128 + 4 * tm);    // pairs 4,5
            ulonglong2 A3 = *(const ulonglong2*)(ak + 192 + 4 * tm);    // pairs 6,7
            float4 b0 = *(const float4*)(bk + 4 * tn);
            float4 b1 = *(const float4*)(bk + 64 + 4 * tn);
            ull bd[8];
            bd[0] = dup2(b0.x); bd[1] = dup2(b0.y); bd[2] = dup2(b0.z); bd[3] = dup2(b0.w);
            bd[4] = dup2(b1.x); bd[5] = dup2(b1.y); bd[6] = dup2(b1.z); bd[7] = dup2(b1.w);
            #pragma unroll
            for (int n = 0; n < 8; n++) {
                ffma2(acc[0][n], A0.x, bd[n]);
                ffma2(acc[1][n], A0.y, bd[n]);
                ffma2(acc[2][n], A1.x, bd[n]);
                ffma2(acc[3][n], A1.y, bd[n]);
                ffma2(acc[4][n], A2.x, bd[n]);
                ffma2(acc[5][n], A2.y, bd[n]);
                ffma2(acc[6][n], A3.x, bd[n]);
                ffma2(acc[7][n], A3.y, bd[n]);
            }
        }
        __syncthreads();
    }

    if (half == 0) {
        // write p0
        #pragma unroll
        for (int p = 0; p < 8; p++) {
            float o0[8], o1[8];
            #pragma unroll
            for (int n = 0; n < 8; n++) {
                float2 v = unpk(acc[p][n]);
                o0[n] = v.x; o1[n] = v.y;
            }
            float* c0 = g_p0 + (size_t)(m0 + 16 * tm + 2 * p) * N_HID + n0 + 8 * tn;
            float* c1 = c0 + N_HID;
            *(float4*)(c0)     = make_float4(o0[0], o0[1], o0[2], o0[3]);
            *(float4*)(c0 + 4) = make_float4(o0[4], o0[5], o0[6], o0[7]);
            *(float4*)(c1)     = make_float4(o1[0], o1[1], o1[2], o1[3]);
            *(float4*)(c1 + 4) = make_float4(o1[4], o1[5], o1[6], o1[7]);
        }
    } else {
        // out = (p0 + p1) + bias  (exact R9 epilogue order)
        float bv[8];
        *(float4*)&bv[0] = *(const float4*)&bias[n0 + 8 * tn];
        *(float4*)&bv[4] = *(const float4*)&bias[n0 + 8 * tn + 4];
        #pragma unroll
        for (int p = 0; p < 8; p++) {
            const float* q0 = g_p0 + (size_t)(m0 + 16 * tm + 2 * p) * N_HID + n0 + 8 * tn;
            const float* q1 = q0 + N_HID;
            float p00[8], p01[8];
            *(float4*)&p00[0] = *(const float4*)(q0);
            *(float4*)&p00[4] = *(const float4*)(q0 + 4);
            *(float4*)&p01[0] = *(const float4*)(q1);
            *(float4*)&p01[4] = *(const float4*)(q1 + 4);
            float o0[8], o1[8];
            #pragma unroll
            for (int n = 0; n < 8; n++) {
                float2 v = unpk(acc[p][n]);
                o0[n] = __fadd_rn(__fadd_rn(p00[n], v.x), bv[n]);
                o1[n] = __fadd_rn(__fadd_rn(p01[n], v.y), bv[n]);
            }
            float* c0 = g_cur1 + (size_t)(m0 + 16 * tm + 2 * p) * N_HID + n0 + 8 * tn;
            float* c1 = c0 + N_HID;
            *(float4*)(c0)     = make_float4(o0[0], o0[1], o0[2], o0[3]);
            *(float4*)(c0 + 4) = make_float4(o0[4], o0[5], o0[6], o0[7]);
            *(float4*)(c1)     = make_float4(o1[0], o1[1], o1[2], o1[3]);
            *(float4*)(c1 + 4) = make_float4(o1[4], o1[5], o1[6], o1[7]);
        }
    }
}

// ---------------------------------------------------------------------------
// LIF update (de-contracted; validated R9)
// ---------------------------------------------------------------------------
__device__ __forceinline__ void lif_update(float m, float c, float& nm, float& sp) {
    float t0 = __fmul_rn(BETA, m);
    float t1 = __fadd_rn(t0, c);
    float rst = (m > THRESH) ? THRESH : 0.0f;
    nm = __fsub_rn(t1, rst);
    sp = (nm > THRESH) ? 1.0f : 0.0f;
}

// ---------------------------------------------------------------------------
// Fused per-timestep kernel (VERBATIM R13): LIF-1 + ordered compaction +
// sparse gather-sum (bitwise == dense ascending-k chain) + LIF-2.
// ---------------------------------------------------------------------------
__global__ __launch_bounds__(256) void step_fused_kernel(
    int t,
    const float* __restrict__ b2,
    float* __restrict__ out_spk,
    float* __restrict__ out_mem)
{
    const int m = blockIdx.x;
    const int tid = threadIdx.x;
    const int lane = tid & 31;
    const int wid = tid >> 5;

    __shared__ int sidx[N_HID];
    __shared__ int warp_tot[8];
    __shared__ int warp_base[8];
    __shared__ int pass_base;

    if (tid == 0) pass_base = 0;
    __syncthreads();

    const float* cur = g_cur1 + (size_t)t * BATCH * N_HID + (size_t)m * N_HID;
    float* memr = g_mem1 + (size_t)m * N_HID;

    #pragma unroll 1
    for (int pass = 0; pass < 4; pass++) {
        const int i0 = pass * 1024 + tid * 4;
        float4 c = *(const float4*)(cur + i0);
        float4 mm = *(const float4*)(memr + i0);
        float4 nm; float sp[4];
        lif_update(mm.x, c.x, nm.x, sp[0]);
        lif_update(mm.y, c.y, nm.y, sp[1]);
        lif_update(mm.z, c.z, nm.z, sp[2]);
        lif_update(mm.w, c.w, nm.w, sp[3]);
        *(float4*)(memr + i0) = nm;

        int bits = (sp[0] > 0.0f ? 1 : 0) | (sp[1] > 0.0f ? 2 : 0)
                 | (sp[2] > 0.0f ? 4 : 0) | (sp[3] > 0.0f ? 8 : 0);
        int cnt = __popc(bits);

        int pre = cnt;
        #pragma unroll
        for (int d = 1; d < 32; d <<= 1) {
            int v = __shfl_up_sync(0xFFFFFFFFu, pre, d);
            if (lane >= d) pre += v;
        }
        int excl = pre - cnt;
        if (lane == 31) warp_tot[wid] = pre;
        __syncthreads();

        if (tid == 0) {
            int s = pass_base;
            #pragma unroll
            for (int w = 0; w < 8; w++) { warp_base[w] = s; s += warp_tot[w]; }
            pass_base = s;
        }
        __syncthreads();

        int off = warp_base[wid] + excl;
        #pragma unroll
        for (int j = 0; j < 4; j++)
            if ((bits >> j) & 1) sidx[off++] = i0 + j;
        __syncthreads();
    }

    const int cnt = pass_base;
    const int n2 = tid * 2;

    float accx = 0.0f, accy = 0.0f;
    int j = 0;
    for (; j + 4 <= cnt; j += 4) {
        int k0 = sidx[j], k1 = sidx[j + 1], k2 = sidx[j + 2], k3 = sidx[j + 3];
        float2 w0 = *(const float2*)(g_W2T + (size_t)k0 * N_OUT + n2);
        float2 w1 = *(const float2*)(g_W2T + (size_t)k1 * N_OUT + n2);
        float2 w2 = *(const float2*)(g_W2T + (size_t)k2 * N_OUT + n2);
        float2 w3 = *(const float2*)(g_W2T + (size_t)k3 * N_OUT + n2);
        accx = __fadd_rn(accx, w0.x); accy = __fadd_rn(accy, w0.y);
        accx = __fadd_rn(accx, w1.x); accy = __fadd_rn(accy, w1.y);
        accx = __fadd_rn(accx, w2.x); accy = __fadd_rn(accy, w2.y);
        accx = __fadd_rn(accx, w3.x); accy = __fadd_rn(accy, w3.y);
    }
    for (; j < cnt; j++) {
        int k = sidx[j];
        float2 w = *(const float2*)(g_W2T + (size_t)k * N_OUT + n2);
        accx = __fadd_rn(accx, w.x); accy = __fadd_rn(accy, w.y);
    }

    float2 bb = *(const float2*)(b2 + n2);
    float cx = __fadd_rn(accx, bb.x);
    float cy = __fadd_rn(accy, bb.y);
    float2 mo = *(const float2*)(g_mem2 + (size_t)m * N_OUT + n2);
    float nmx, nmy, spx, spy;
    lif_update(mo.x, cx, nmx, spx);
    lif_update(mo.y, cy, nmy, spy);
    *(float2*)(g_mem2 + (size_t)m * N_OUT + n2) = make_float2(nmx, nmy);
    *(float2*)(out_spk + (size_t)m * N_OUT + n2) = make_float2(spx, spy);
    *(float2*)(out_mem + (size_t)m * N_OUT + n2) = make_float2(nmx, nmy);
}

// ---------------------------------------------------------------------------
// Launch: two-stream fork/join captured in the graph. gemm1 chunks (stream 0)
// gate step chunks (stream s2) via events; steps overlap gemm1 (disjoint
// bottlenecks: FMA pipe vs L2).
// ---------------------------------------------------------------------------
extern "C" void kernel_launch(void* const* d_in, const int* in_sizes, int n_in,
                              void* d_out, int out_size) {
    const float* x  = (const float*)d_in[0];
    const float* W1 = (const float*)d_in[1];
    const float* b1 = (const float*)d_in[2];
    const float* W2 = (const float*)d_in[3];
    const float* b2 = (const float*)d_in[4];
    float* out = (float*)d_out;

    static cudaStream_t s2 = nullptr;
    static cudaEvent_t evc[NCHUNK], evj;
    if (s2 == nullptr) {
        cudaStreamCreateWithFlags(&s2, cudaStreamNonBlocking);
        for (int i = 0; i < NCHUNK; i++)
            cudaEventCreateWithFlags(&evc[i], cudaEventDisableTiming);
        cudaEventCreateWithFlags(&evj, cudaEventDisableTiming);
    }

    init_kernel<<<(BATCH * N_HID + 255) / 256, 256>>>();
    {
        dim3 gT(N_HID / 32, N_OUT / 32);
        transpose_w2_kernel<<<gT, 256>>>(W2);
    }

    // Stream 0: gemm1 in NCHUNK t-chunks (half1 then half2), event per chunk.
    for (int c = 0; c < NCHUNK; c++) {
        int m_base = c * TCHUNK * BATCH;                 // 2560 rows per chunk
        dim3 grid(N_HID / 128, TCHUNK * BATCH / 256);    // (32, 10)
        gemm1_half_kernel<<<grid, 256>>>(x, W1, b1, m_base, 0);
        gemm1_half_kernel<<<grid, 256>>>(x, W1, b1, m_base, 1);
        cudaEventRecord(evc[c], 0);
    }

    float* out_spk_base = out;
    float* out_mem_base = out + (size_t)T_STEPS * BATCH * N_OUT;

    // Stream s2: step recurrence, gated per chunk.
    for (int c = 0; c < NCHUNK; c++) {
        cudaStreamWaitEvent(s2, evc[c], 0);
        for (int t = c * TCHUNK; t < (c + 1) * TCHUNK; t++) {
            step_fused_kernel<<<BATCH, 256, 0, s2>>>(
                t, b2,
                out_spk_base + (size_t)t * BATCH * N_OUT,
                out_mem_base + (size_t)t * BATCH * N_OUT);
        }
    }
    cudaEventRecord(evj, s2);
    cudaStreamWaitEvent(0, evj, 0);   // join: stream 0 completes only after all steps
}

// round 15
// speedup vs baseline: 1.2343x; 1.2343x over previous
#include <cuda_runtime.h>

// Problem constants
#define T_STEPS 100
#define BATCH   256
#define N_IN    1024
#define N_HID   4096
#define N_OUT   512
#define KHALF   512            // gemm1 split-K=2 boundary (validated R9)
#define NCHUNK  10             // t-chunks for gemm1/step overlap
#define TCHUNK  (T_STEPS / NCHUNK)

#define BETA   0.95f
#define THRESH 1.0f

typedef unsigned long long ull;

// Packed fp32x2: each lane is an independent IEEE fp32 RN FMA -> packed
// accumulators hold two independent scalar fmaf chains, bitwise identical.
__device__ __forceinline__ ull dup2(float x) {
    ull r; asm("mov.b64 %0, {%1, %1};" : "=l"(r) : "f"(x)); return r;
}
__device__ __forceinline__ void ffma2(ull& acc, ull a, ull b) {
    asm("fma.rn.f32x2 %0, %1, %2, %0;" : "+l"(acc) : "l"(a), "l"(b));
}
__device__ __forceinline__ float2 unpk(ull v) {
    float2 f; asm("mov.b64 {%0, %1}, %2;" : "=f"(f.x), "=f"(f.y) : "l"(v)); return f;
}

// ---------------------------------------------------------------------------
// RULE: __device__ globals are referenced ONLY inside device code.
// ---------------------------------------------------------------------------
__device__ float g_cur1[(size_t)T_STEPS * BATCH * N_HID];   // 419 MB
__device__ float g_p0  [(size_t)T_STEPS * BATCH * N_HID];   // 419 MB split-K p0
__device__ float g_mem1[BATCH * N_HID];
__device__ float g_mem2[BATCH * N_OUT];
__device__ float g_W2T[(size_t)N_HID * N_OUT];              // 8 MB transposed W2

__global__ void init_kernel() {
    int i = blockIdx.x * blockDim.x + threadIdx.x;
    if (i < BATCH * N_HID) g_mem1[i] = 0.0f;
    if (i < BATCH * N_OUT) g_mem2[i] = 0.0f;
}

// ---------------------------------------------------------------------------
// One-time transpose: g_W2T[k][n] = W2[n][k].
// ---------------------------------------------------------------------------
__global__ __launch_bounds__(256) void transpose_w2_kernel(const float* __restrict__ W2) {
    __shared__ float tile[32][33];
    const int k0 = blockIdx.x * 32;
    const int n0 = blockIdx.y * 32;
    const int tx = threadIdx.x & 31;
    const int ty = threadIdx.x >> 5;
    #pragma unroll
    for (int i = 0; i < 4; i++)
        tile[ty + i * 8][tx] = W2[(size_t)(n0 + ty + i * 8) * N_HID + k0 + tx];
    __syncthreads();
    #pragma unroll
    for (int i = 0; i < 4; i++)
        g_W2T[(size_t)(k0 + ty + i * 8) * N_OUT + n0 + tx] = tile[tx][ty + i * 8];
}

// ---------------------------------------------------------------------------
// GEMM1 v4: one k-half per launch, 128x128 tile, BK=16, 256 threads,
// 8m x 8n per thread -> 32 packed (m-pair) accumulators = 64 regs, 2 blocks/SM.
// half=0: acc = chain(k 0..511), write p0.
// half=1: acc = chain(k 512..1023), out = ((p0 + acc) + bias) -> g_cur1.
// smem layout (R13-validated): per k-row of 132 floats, element x at
//   off(x) = ((x & 4) << 4) + ((x >> 3) << 2) + (x & 3)
// -> thread t reads 16B chunks at 4*t and 64 + 4*t.
// ---------------------------------------------------------------------------
#define G1_BK  16
#define G1_ROW 132

__device__ __forceinline__ int g1_off(int x) {
    return ((x & 4) << 4) + ((x >> 3) << 2) + (x & 3);
}

__global__ __launch_bounds__(256, 2) void gemm1_half_kernel(
    const float* __restrict__ A,     // [25600, N_IN]
    const float* __restrict__ W,     // [N_HID, N_IN]
    const float* __restrict__ bias,  // [N_HID]
    int m_base, int half)
{
    __shared__ float As[G1_BK * G1_ROW];
    __shared__ float Bs[G1_BK * G1_ROW];

    const int tid = threadIdx.x;
    const int m0 = m_base + blockIdx.y * 128;
    const int n0 = blockIdx.x * 128;
    const int tm = tid >> 4;          // 0..15 -> rows m0+8*tm..+7
    const int tn = tid & 15;          // 0..15 -> cols n0+8*tn..+7

    const int kbeg = half ? KHALF : 0;
    const int kend = kbeg + KHALF;

    ull acc[4][8];                    // [m-pair][n]
    #pragma unroll
    for (int p = 0; p < 4; p++)
        #pragma unroll
        for (int n = 0; n < 8; n++) acc[p][n] = 0ULL;

    int lr[2], lkv[2];
    #pragma unroll
    for (int i = 0; i < 2; i++) {
        int l = tid + (i << 8);
        lr[i]  = l >> 2;              // 0..127
        lkv[i] = (l & 3) << 2;        // 0,4,8,12
    }

    float4 pa[2], pb[2];
    #pragma unroll
    for (int i = 0; i < 2; i++) {
        pa[i] = *(const float4*)(A + (size_t)(m0 + lr[i]) * N_IN + kbeg + lkv[i]);
        pb[i] = *(const float4*)(W + (size_t)(n0 + lr[i]) * N_IN + kbeg + lkv[i]);
    }

    for (int k0 = kbeg; k0 < kend; k0 += G1_BK) {
        #pragma unroll
        for (int i = 0; i < 2; i++) {
            int o = g1_off(lr[i]);
            As[(lkv[i] + 0) * G1_ROW + o] = pa[i].x;
            As[(lkv[i] + 1) * G1_ROW + o] = pa[i].y;
            As[(lkv[i] + 2) * G1_ROW + o] = pa[i].z;
            As[(lkv[i] + 3) * G1_ROW + o] = pa[i].w;
            Bs[(lkv[i] + 0) * G1_ROW + o] = pb[i].x;
            Bs[(lkv[i] + 1) * G1_ROW + o] = pb[i].y;
            Bs[(lkv[i] + 2) * G1_ROW + o] = pb[i].z;
            Bs[(lkv[i] + 3) * G1_ROW + o] = pb[i].w;
        }
        __syncthreads();

        if (k0 + G1_BK < kend) {
            #pragma unroll
            for (int i = 0; i < 2; i++) {
                pa[i] = *(const float4*)(A + (size_t)(m0 + lr[i]) * N_IN + k0 + G1_BK + lkv[i]);
                pb[i] = *(const float4*)(W + (size_t)(n0 + lr[i]) * N_IN + k0 + G1_BK + lkv[i]);
            }
        }

        #pragma unroll
        for (int kk = 0; kk < G1_BK; kk++) {
            const float* ak = As + kk * G1_ROW;
            const float* bk = Bs + kk * G1_ROW;
            ulonglong2 A0 = *(const ulonglong2*)(ak + 4 * tm);        // m-pairs 0,1
            ulonglong2 A1 = *(const ulonglong2*)(ak + 64 + 4 * tm);   // m-pairs 2,3
            float4 b0 = *(const float4*)(bk + 4 * tn);
            float4 b1 = *(const float4*)(bk + 64 + 4 * tn);
            ull bd[8];
            bd[0] = dup2(b0.x); bd[1] = dup2(b0.y); bd[2] = dup2(b0.z); bd[3] = dup2(b0.w);
            bd[4] = dup2(b1.x); bd[5] = dup2(b1.y); bd[6] = dup2(b1.z); bd[7] = dup2(b1.w);
            #pragma unroll
            for (int n = 0; n < 8; n++) {
                ffma2(acc[0][n], A0.x, bd[n]);
                ffma2(acc[1][n], A0.y, bd[n]);
                ffma2(acc[2][n], A1.x, bd[n]);
                ffma2(acc[3][n], A1.y, bd[n]);
            }
        }
        __syncthreads();
    }

    if (half == 0) {
        #pragma unroll
        for (int p = 0; p < 4; p++) {
            float o0[8], o1[8];
            #pragma unroll
            for (int n = 0; n < 8; n++) {
                float2 v = unpk(acc[p][n]);
                o0[n] = v.x; o1[n] = v.y;
            }
            float* c0 = g_p0 + (size_t)(m0 + 8 * tm + 2 * p) * N_HID + n0 + 8 * tn;
            float* c1 = c0 + N_HID;
            *(float4*)(c0)     = make_float4(o0[0], o0[1], o0[2], o0[3]);
            *(float4*)(c0 + 4) = make_float4(o0[4], o0[5], o0[6], o0[7]);
            *(float4*)(c1)     = make_float4(o1[0], o1[1], o1[2], o1[3]);
            *(float4*)(c1 + 4) = make_float4(o1[4], o1[5], o1[6], o1[7]);
        }
    } else {
        // out = (p0 + p1) + bias  (exact R9-validated epilogue order)
        float bv[8];
        *(float4*)&bv[0] = *(const float4*)&bias[n0 + 8 * tn];
        *(float4*)&bv[4] = *(const float4*)&bias[n0 + 8 * tn + 4];
        #pragma unroll
        for (int p = 0; p < 4; p++) {
            const float* q0 = g_p0 + (size_t)(m0 + 8 * tm + 2 * p) * N_HID + n0 + 8 * tn;
            const float* q1 = q0 + N_HID;
            float p00[8], p01[8];
            *(float4*)&p00[0] = *(const float4*)(q0);
            *(float4*)&p00[4] = *(const float4*)(q0 + 4);
            *(float4*)&p01[0] = *(const float4*)(q1);
            *(float4*)&p01[4] = *(const float4*)(q1 + 4);
            float o0[8], o1[8];
            #pragma unroll
            for (int n = 0; n < 8; n++) {
                float2 v = unpk(acc[p][n]);
                o0[n] = __fadd_rn(__fadd_rn(p00[n], v.x), bv[n]);
                o1[n] = __fadd_rn(__fadd_rn(p01[n], v.y), bv[n]);
            }
            float* c0 = g_cur1 + (size_t)(m0 + 8 * tm + 2 * p) * N_HID + n0 + 8 * tn;
            float* c1 = c0 + N_HID;
            *(float4*)(c0)     = make_float4(o0[0], o0[1], o0[2], o0[3]);
            *(float4*)(c0 + 4) = make_float4(o0[4], o0[5], o0[6], o0[7]);
            *(float4*)(c1)     = make_float4(o1[0], o1[1], o1[2], o1[3]);
            *(float4*)(c1 + 4) = make_float4(o1[4], o1[5], o1[6], o1[7]);
        }
    }
}

// ---------------------------------------------------------------------------
// LIF update (de-contracted; validated R9)
// ---------------------------------------------------------------------------
__device__ __forceinline__ void lif_update(float m, float c, float& nm, float& sp) {
    float t0 = __fmul_rn(BETA, m);
    float t1 = __fadd_rn(t0, c);
    float rst = (m > THRESH) ? THRESH : 0.0f;
    nm = __fsub_rn(t1, rst);
    sp = (nm > THRESH) ? 1.0f : 0.0f;
}

// ---------------------------------------------------------------------------
// Fused per-timestep kernel (VERBATIM R13): LIF-1 + ordered compaction +
// sparse gather-sum (bitwise == dense ascending-k chain) + LIF-2.
// ---------------------------------------------------------------------------
__global__ __launch_bounds__(256) void step_fused_kernel(
    int t,
    const float* __restrict__ b2,
    float* __restrict__ out_spk,
    float* __restrict__ out_mem)
{
    const int m = blockIdx.x;
    const int tid = threadIdx.x;
    const int lane = tid & 31;
    const int wid = tid >> 5;

    __shared__ int sidx[N_HID];
    __shared__ int warp_tot[8];
    __shared__ int warp_base[8];
    __shared__ int pass_base;

    if (tid == 0) pass_base = 0;
    __syncthreads();

    const float* cur = g_cur1 + (size_t)t * BATCH * N_HID + (size_t)m * N_HID;
    float* memr = g_mem1 + (size_t)m * N_HID;

    #pragma unroll 1
    for (int pass = 0; pass < 4; pass++) {
        const int i0 = pass * 1024 + tid * 4;
        float4 c = *(const float4*)(cur + i0);
        float4 mm = *(const float4*)(memr + i0);
        float4 nm; float sp[4];
        lif_update(mm.x, c.x, nm.x, sp[0]);
        lif_update(mm.y, c.y, nm.y, sp[1]);
        lif_update(mm.z, c.z, nm.z, sp[2]);
        lif_update(mm.w, c.w, nm.w, sp[3]);
        *(float4*)(memr + i0) = nm;

        int bits = (sp[0] > 0.0f ? 1 : 0) | (sp[1] > 0.0f ? 2 : 0)
                 | (sp[2] > 0.0f ? 4 : 0) | (sp[3] > 0.0f ? 8 : 0);
        int cnt = __popc(bits);

        int pre = cnt;
        #pragma unroll
        for (int d = 1; d < 32; d <<= 1) {
            int v = __shfl_up_sync(0xFFFFFFFFu, pre, d);
            if (lane >= d) pre += v;
        }
        int excl = pre - cnt;
        if (lane == 31) warp_tot[wid] = pre;
        __syncthreads();

        if (tid == 0) {
            int s = pass_base;
            #pragma unroll
            for (int w = 0; w < 8; w++) { warp_base[w] = s; s += warp_tot[w]; }
            pass_base = s;
        }
        __syncthreads();

        int off = warp_base[wid] + excl;
        #pragma unroll
        for (int j = 0; j < 4; j++)
            if ((bits >> j) & 1) sidx[off++] = i0 + j;
        __syncthreads();
    }

    const int cnt = pass_base;
    const int n2 = tid * 2;

    float accx = 0.0f, accy = 0.0f;
    int j = 0;
    for (; j + 4 <= cnt; j += 4) {
        int k0 = sidx[j], k1 = sidx[j + 1], k2 = sidx[j + 2], k3 = sidx[j + 3];
        float2 w0 = *(const float2*)(g_W2T + (size_t)k0 * N_OUT + n2);
        float2 w1 = *(const float2*)(g_W2T + (size_t)k1 * N_OUT + n2);
        float2 w2 = *(const float2*)(g_W2T + (size_t)k2 * N_OUT + n2);
        float2 w3 = *(const float2*)(g_W2T + (size_t)k3 * N_OUT + n2);
        accx = __fadd_rn(accx, w0.x); accy = __fadd_rn(accy, w0.y);
        accx = __fadd_rn(accx, w1.x); accy = __fadd_rn(accy, w1.y);
        accx = __fadd_rn(accx, w2.x); accy = __fadd_rn(accy, w2.y);
        accx = __fadd_rn(accx, w3.x); accy = __fadd_rn(accy, w3.y);
    }
    for (; j < cnt; j++) {
        int k = sidx[j];
        float2 w = *(const float2*)(g_W2T + (size_t)k * N_OUT + n2);
        accx = __fadd_rn(accx, w.x); accy = __fadd_rn(accy, w.y);
    }

    float2 bb = *(const float2*)(b2 + n2);
    float cx = __fadd_rn(accx, bb.x);
    float cy = __fadd_rn(accy, bb.y);
    float2 mo = *(const float2*)(g_mem2 + (size_t)m * N_OUT + n2);
    float nmx, nmy, spx, spy;
    lif_update(mo.x, cx, nmx, spx);
    lif_update(mo.y, cy, nmy, spy);
    *(float2*)(g_mem2 + (size_t)m * N_OUT + n2) = make_float2(nmx, nmy);
    *(float2*)(out_spk + (size_t)m * N_OUT + n2) = make_float2(spx, spy);
    *(float2*)(out_mem + (size_t)m * N_OUT + n2) = make_float2(nmx, nmy);
}

// ---------------------------------------------------------------------------
// Launch: two-stream fork/join captured in the graph (validated R14).
// ---------------------------------------------------------------------------
extern "C" void kernel_launch(void* const* d_in, const int* in_sizes, int n_in,
                              void* d_out, int out_size) {
    const float* x  = (const float*)d_in[0];
    const float* W1 = (const float*)d_in[1];
    const float* b1 = (const float*)d_in[2];
    const float* W2 = (const float*)d_in[3];
    const float* b2 = (const float*)d_in[4];
    float* out = (float*)d_out;

    static cudaStream_t s2 = nullptr;
    static cudaEvent_t evc[NCHUNK], evj;
    if (s2 == nullptr) {
        cudaStreamCreateWithFlags(&s2, cudaStreamNonBlocking);
        for (int i = 0; i < NCHUNK; i++)
            cudaEventCreateWithFlags(&evc[i], cudaEventDisableTiming);
        cudaEventCreateWithFlags(&evj, cudaEventDisableTiming);
    }

    init_kernel<<<(BATCH * N_HID + 255) / 256, 256>>>();
    {
        dim3 gT(N_HID / 32, N_OUT / 32);
        transpose_w2_kernel<<<gT, 256>>>(W2);
    }

    // Stream 0: gemm1 in NCHUNK t-chunks (half0 then half1), event per chunk.
    for (int c = 0; c < NCHUNK; c++) {
        int m_base = c * TCHUNK * BATCH;                 // 2560 rows per chunk
        dim3 grid(N_HID / 128, TCHUNK * BATCH / 128);    // (32, 20)
        gemm1_half_kernel<<<grid, 256>>>(x, W1, b1, m_base, 0);
        gemm1_half_kernel<<<grid, 256>>>(x, W1, b1, m_base, 1);
        cudaEventRecord(evc[c], 0);
    }

    float* out_spk_base = out;
    float* out_mem_base = out + (size_t)T_STEPS * BATCH * N_OUT;

    // Stream s2: step recurrence, gated per chunk.
    for (int c = 0; c < NCHUNK; c++) {
        cudaStreamWaitEvent(s2, evc[c], 0);
        for (int t = c * TCHUNK; t < (c + 1) * TCHUNK; t++) {
            step_fused_kernel<<<BATCH, 256, 0, s2>>>(
                t, b2,
                out_spk_base + (size_t)t * BATCH * N_OUT,
                out_mem_base + (size_t)t * BATCH * N_OUT);
        }
    }
    cudaEventRecord(evj, s2);
    cudaStreamWaitEvent(0, evj, 0);   // join
}

// round 16
// speedup vs baseline: 1.3060x; 1.0581x over previous
#include <cuda_runtime.h>

// Problem constants
#define T_STEPS 100
#define BATCH   256
#define N_IN    1024
#define N_HID   4096
#define N_OUT   512
#define KHALF   512            // gemm1 split-K=2 boundary (validated R9)
#define NCHUNK  20             // t-chunks (5 t each) for packed overlap
#define TCHUNK  (T_STEPS / NCHUNK)
#define ROWCHUNK (TCHUNK * BATCH)   // 1280 rows per chunk

#define BETA   0.95f
#define THRESH 1.0f

typedef unsigned long long ull;

// Packed fp32x2: each lane is an independent IEEE fp32 RN FMA -> packed
// accumulators hold two independent scalar fmaf chains, bitwise identical.
__device__ __forceinline__ ull dup2(float x) {
    ull r; asm("mov.b64 %0, {%1, %1};" : "=l"(r) : "f"(x)); return r;
}
__device__ __forceinline__ void ffma2(ull& acc, ull a, ull b) {
    asm("fma.rn.f32x2 %0, %1, %2, %0;" : "+l"(acc) : "l"(a), "l"(b));
}
__device__ __forceinline__ float2 unpk(ull v) {
    float2 f; asm("mov.b64 {%0, %1}, %2;" : "=f"(f.x), "=f"(f.y) : "l"(v)); return f;
}

// ---------------------------------------------------------------------------
// RULE: __device__ globals are referenced ONLY inside device code.
// ---------------------------------------------------------------------------
__device__ float g_cur1[(size_t)T_STEPS * BATCH * N_HID];   // 419 MB
__device__ float g_p0  [(size_t)T_STEPS * BATCH * N_HID];   // 419 MB split-K p0
__device__ float g_mem1[BATCH * N_HID];
__device__ float g_mem2[BATCH * N_OUT];
__device__ float g_W2T[(size_t)N_HID * N_OUT];              // 8 MB transposed W2

__global__ void init_kernel() {
    int i = blockIdx.x * blockDim.x + threadIdx.x;
    if (i < BATCH * N_HID) g_mem1[i] = 0.0f;
    if (i < BATCH * N_OUT) g_mem2[i] = 0.0f;
}

// ---------------------------------------------------------------------------
// One-time transpose: g_W2T[k][n] = W2[n][k].
// ---------------------------------------------------------------------------
__global__ __launch_bounds__(256) void transpose_w2_kernel(const float* __restrict__ W2) {
    __shared__ float tile[32][33];
    const int k0 = blockIdx.x * 32;
    const int n0 = blockIdx.y * 32;
    const int tx = threadIdx.x & 31;
    const int ty = threadIdx.x >> 5;
    #pragma unroll
    for (int i = 0; i < 4; i++)
        tile[ty + i * 8][tx] = W2[(size_t)(n0 + ty + i * 8) * N_HID + k0 + tx];
    __syncthreads();
    #pragma unroll
    for (int i = 0; i < 4; i++)
        g_W2T[(size_t)(k0 + ty + i * 8) * N_OUT + n0 + tx] = tile[tx][ty + i * 8];
}

// ---------------------------------------------------------------------------
// GEMM1 (VERBATIM R15, bitwise-validated): one k-half per launch, 128x128
// tile, BK=16, 256 threads, 8m x 8n per thread, 2 blocks/SM.
// half=0: acc = chain(k 0..511) -> p0.   half=1: ((p0 + acc) + bias) -> cur1.
// ---------------------------------------------------------------------------
#define G1_BK  16
#define G1_ROW 132

__device__ __forceinline__ int g1_off(int x) {
    return ((x & 4) << 4) + ((x >> 3) << 2) + (x & 3);
}

__global__ __launch_bounds__(256, 2) void gemm1_half_kernel(
    const float* __restrict__ A,     // [25600, N_IN]
    const float* __restrict__ W,     // [N_HID, N_IN]
    const float* __restrict__ bias,  // [N_HID]
    int m_base, int half)
{
    __shared__ float As[G1_BK * G1_ROW];
    __shared__ float Bs[G1_BK * G1_ROW];

    const int tid = threadIdx.x;
    const int m0 = m_base + blockIdx.y * 128;
    const int n0 = blockIdx.x * 128;
    const int tm = tid >> 4;
    const int tn = tid & 15;

    const int kbeg = half ? KHALF : 0;
    const int kend = kbeg + KHALF;

    ull acc[4][8];
    #pragma unroll
    for (int p = 0; p < 4; p++)
        #pragma unroll
        for (int n = 0; n < 8; n++) acc[p][n] = 0ULL;

    int lr[2], lkv[2];
    #pragma unroll
    for (int i = 0; i < 2; i++) {
        int l = tid + (i << 8);
        lr[i]  = l >> 2;
        lkv[i] = (l & 3) << 2;
    }

    float4 pa[2], pb[2];
    #pragma unroll
    for (int i = 0; i < 2; i++) {
        pa[i] = *(const float4*)(A + (size_t)(m0 + lr[i]) * N_IN + kbeg + lkv[i]);
        pb[i] = *(const float4*)(W + (size_t)(n0 + lr[i]) * N_IN + kbeg + lkv[i]);
    }

    for (int k0 = kbeg; k0 < kend; k0 += G1_BK) {
        #pragma unroll
        for (int i = 0; i < 2; i++) {
            int o = g1_off(lr[i]);
            As[(lkv[i] + 0) * G1_ROW + o] = pa[i].x;
            As[(lkv[i] + 1) * G1_ROW + o] = pa[i].y;
            As[(lkv[i] + 2) * G1_ROW + o] = pa[i].z;
            As[(lkv[i] + 3) * G1_ROW + o] = pa[i].w;
            Bs[(lkv[i] + 0) * G1_ROW + o] = pb[i].x;
            Bs[(lkv[i] + 1) * G1_ROW + o] = pb[i].y;
            Bs[(lkv[i] + 2) * G1_ROW + o] = pb[i].z;
            Bs[(lkv[i] + 3) * G1_ROW + o] = pb[i].w;
        }
        __syncthreads();

        if (k0 + G1_BK < kend) {
            #pragma unroll
            for (int i = 0; i < 2; i++) {
                pa[i] = *(const float4*)(A + (size_t)(m0 + lr[i]) * N_IN + k0 + G1_BK + lkv[i]);
                pb[i] = *(const float4*)(W + (size_t)(n0 + lr[i]) * N_IN + k0 + G1_BK + lkv[i]);
            }
        }

        #pragma unroll
        for (int kk = 0; kk < G1_BK; kk++) {
            const float* ak = As + kk * G1_ROW;
            const float* bk = Bs + kk * G1_ROW;
            ulonglong2 A0 = *(const ulonglong2*)(ak + 4 * tm);
            ulonglong2 A1 = *(const ulonglong2*)(ak + 64 + 4 * tm);
            float4 b0 = *(const float4*)(bk + 4 * tn);
            float4 b1 = *(const float4*)(bk + 64 + 4 * tn);
            ull bd[8];
            bd[0] = dup2(b0.x); bd[1] = dup2(b0.y); bd[2] = dup2(b0.z); bd[3] = dup2(b0.w);
            bd[4] = dup2(b1.x); bd[5] = dup2(b1.y); bd[6] = dup2(b1.z); bd[7] = dup2(b1.w);
            #pragma unroll
            for (int n = 0; n < 8; n++) {
                ffma2(acc[0][n], A0.x, bd[n]);
                ffma2(acc[1][n], A0.y, bd[n]);
                ffma2(acc[2][n], A1.x, bd[n]);
                ffma2(acc[3][n], A1.y, bd[n]);
            }
        }
        __syncthreads();
    }

    if (half == 0) {
        #pragma unroll
        for (int p = 0; p < 4; p++) {
            float o0[8], o1[8];
            #pragma unroll
            for (int n = 0; n < 8; n++) {
                float2 v = unpk(acc[p][n]);
                o0[n] = v.x; o1[n] = v.y;
            }
            float* c0 = g_p0 + (size_t)(m0 + 8 * tm + 2 * p) * N_HID + n0 + 8 * tn;
            float* c1 = c0 + N_HID;
            *(float4*)(c0)     = make_float4(o0[0], o0[1], o0[2], o0[3]);
            *(float4*)(c0 + 4) = make_float4(o0[4], o0[5], o0[6], o0[7]);
            *(float4*)(c1)     = make_float4(o1[0], o1[1], o1[2], o1[3]);
            *(float4*)(c1 + 4) = make_float4(o1[4], o1[5], o1[6], o1[7]);
        }
    } else {
        float bv[8];
        *(float4*)&bv[0] = *(const float4*)&bias[n0 + 8 * tn];
        *(float4*)&bv[4] = *(const float4*)&bias[n0 + 8 * tn + 4];
        #pragma unroll
        for (int p = 0; p < 4; p++) {
            const float* q0 = g_p0 + (size_t)(m0 + 8 * tm + 2 * p) * N_HID + n0 + 8 * tn;
            const float* q1 = q0 + N_HID;
            float p00[8], p01[8];
            *(float4*)&p00[0] = *(const float4*)(q0);
            *(float4*)&p00[4] = *(const float4*)(q0 + 4);
            *(float4*)&p01[0] = *(const float4*)(q1);
            *(float4*)&p01[4] = *(const float4*)(q1 + 4);
            float o0[8], o1[8];
            #pragma unroll
            for (int n = 0; n < 8; n++) {
                float2 v = unpk(acc[p][n]);
                o0[n] = __fadd_rn(__fadd_rn(p00[n], v.x), bv[n]);
                o1[n] = __fadd_rn(__fadd_rn(p01[n], v.y), bv[n]);
            }
            float* c0 = g_cur1 + (size_t)(m0 + 8 * tm + 2 * p) * N_HID + n0 + 8 * tn;
            float* c1 = c0 + N_HID;
            *(float4*)(c0)     = make_float4(o0[0], o0[1], o0[2], o0[3]);
            *(float4*)(c0 + 4) = make_float4(o0[4], o0[5], o0[6], o0[7]);
            *(float4*)(c1)     = make_float4(o1[0], o1[1], o1[2], o1[3]);
            *(float4*)(c1 + 4) = make_float4(o1[4], o1[5], o1[6], o1[7]);
        }
    }
}

// ---------------------------------------------------------------------------
// LIF update (de-contracted; validated R9)
// ---------------------------------------------------------------------------
__device__ __forceinline__ void lif_update(float m, float c, float& nm, float& sp) {
    float t0 = __fmul_rn(BETA, m);
    float t1 = __fadd_rn(t0, c);
    float rst = (m > THRESH) ? THRESH : 0.0f;
    nm = __fsub_rn(t1, rst);
    sp = (nm > THRESH) ? 1.0f : 0.0f;
}

// ---------------------------------------------------------------------------
// Fused per-timestep kernel (VERBATIM R13): LIF-1 + ordered compaction +
// sparse gather-sum (bitwise == dense ascending-k chain) + LIF-2.
// ---------------------------------------------------------------------------
__global__ __launch_bounds__(256) void step_fused_kernel(
    int t,
    const float* __restrict__ b2,
    float* __restrict__ out_spk,
    float* __restrict__ out_mem)
{
    const int m = blockIdx.x;
    const int tid = threadIdx.x;
    const int lane = tid & 31;
    const int wid = tid >> 5;

    __shared__ int sidx[N_HID];
    __shared__ int warp_tot[8];
    __shared__ int warp_base[8];
    __shared__ int pass_base;

    if (tid == 0) pass_base = 0;
    __syncthreads();

    const float* cur = g_cur1 + (size_t)t * BATCH * N_HID + (size_t)m * N_HID;
    float* memr = g_mem1 + (size_t)m * N_HID;

    #pragma unroll 1
    for (int pass = 0; pass < 4; pass++) {
        const int i0 = pass * 1024 + tid * 4;
        float4 c = *(const float4*)(cur + i0);
        float4 mm = *(const float4*)(memr + i0);
        float4 nm; float sp[4];
        lif_update(mm.x, c.x, nm.x, sp[0]);
        lif_update(mm.y, c.y, nm.y, sp[1]);
        lif_update(mm.z, c.z, nm.z, sp[2]);
        lif_update(mm.w, c.w, nm.w, sp[3]);
        *(float4*)(memr + i0) = nm;

        int bits = (sp[0] > 0.0f ? 1 : 0) | (sp[1] > 0.0f ? 2 : 0)
                 | (sp[2] > 0.0f ? 4 : 0) | (sp[3] > 0.0f ? 8 : 0);
        int cnt = __popc(bits);

        int pre = cnt;
        #pragma unroll
        for (int d = 1; d < 32; d <<= 1) {
            int v = __shfl_up_sync(0xFFFFFFFFu, pre, d);
            if (lane >= d) pre += v;
        }
        int excl = pre - cnt;
        if (lane == 31) warp_tot[wid] = pre;
        __syncthreads();

        if (tid == 0) {
            int s = pass_base;
            #pragma unroll
            for (int w = 0; w < 8; w++) { warp_base[w] = s; s += warp_tot[w]; }
            pass_base = s;
        }
        __syncthreads();

        int off = warp_base[wid] + excl;
        #pragma unroll
        for (int j = 0; j < 4; j++)
            if ((bits >> j) & 1) sidx[off++] = i0 + j;
        __syncthreads();
    }

    const int cnt = pass_base;
    const int n2 = tid * 2;

    float accx = 0.0f, accy = 0.0f;
    int j = 0;
    for (; j + 4 <= cnt; j += 4) {
        int k0 = sidx[j], k1 = sidx[j + 1], k2 = sidx[j + 2], k3 = sidx[j + 3];
        float2 w0 = *(const float2*)(g_W2T + (size_t)k0 * N_OUT + n2);
        float2 w1 = *(const float2*)(g_W2T + (size_t)k1 * N_OUT + n2);
        float2 w2 = *(const float2*)(g_W2T + (size_t)k2 * N_OUT + n2);
        float2 w3 = *(const float2*)(g_W2T + (size_t)k3 * N_OUT + n2);
        accx = __fadd_rn(accx, w0.x); accy = __fadd_rn(accy, w0.y);
        accx = __fadd_rn(accx, w1.x); accy = __fadd_rn(accy, w1.y);
        accx = __fadd_rn(accx, w2.x); accy = __fadd_rn(accy, w2.y);
        accx = __fadd_rn(accx, w3.x); accy = __fadd_rn(accy, w3.y);
    }
    for (; j < cnt; j++) {
        int k = sidx[j];
        float2 w = *(const float2*)(g_W2T + (size_t)k * N_OUT + n2);
        accx = __fadd_rn(accx, w.x); accy = __fadd_rn(accy, w.y);
    }

    float2 bb = *(const float2*)(b2 + n2);
    float cx = __fadd_rn(accx, bb.x);
    float cy = __fadd_rn(accy, bb.y);
    float2 mo = *(const float2*)(g_mem2 + (size_t)m * N_OUT + n2);
    float nmx, nmy, spx, spy;
    lif_update(mo.x, cx, nmx, spx);
    lif_update(mo.y, cy, nmy, spy);
    *(float2*)(g_mem2 + (size_t)m * N_OUT + n2) = make_float2(nmx, nmy);
    *(float2*)(out_spk + (size_t)m * N_OUT + n2) = make_float2(spx, spy);
    *(float2*)(out_mem + (size_t)m * N_OUT + n2) = make_float2(nmx, nmy);
}

// ---------------------------------------------------------------------------
// Launch: packed multi-stream schedule (device code unchanged -> bitwise).
//   s0: init, transpose, then evInit.
//   sA/sB (alternating): chunk c = [half0(c); half1(c)] (same-stream ordered);
//                        evS[c] after half1(c). Cross-stream co-scheduling
//                        fills wave tails (each chunk is ~1.08 waves).
//   s2: steps of chunk c gated on evS[c]; serial in t.
//   Join: all streams -> s0.
// ---------------------------------------------------------------------------
extern "C" void kernel_launch(void* const* d_in, const int* in_sizes, int n_in,
                              void* d_out, int out_size) {
    const float* x  = (const float*)d_in[0];
    const float* W1 = (const float*)d_in[1];
    const float* b1 = (const float*)d_in[2];
    const float* W2 = (const float*)d_in[3];
    const float* b2 = (const float*)d_in[4];
    float* out = (float*)d_out;

    static cudaStream_t sA = nullptr, sB = nullptr, s2 = nullptr;
    static cudaEvent_t evInit, evS[NCHUNK], evA, evB, evJ;
    if (sA == nullptr) {
        cudaStreamCreateWithFlags(&sA, cudaStreamNonBlocking);
        cudaStreamCreateWithFlags(&sB, cudaStreamNonBlocking);
        cudaStreamCreateWithFlags(&s2, cudaStreamNonBlocking);
        cudaEventCreateWithFlags(&evInit, cudaEventDisableTiming);
        for (int i = 0; i < NCHUNK; i++)
            cudaEventCreateWithFlags(&evS[i], cudaEventDisableTiming);
        cudaEventCreateWithFlags(&evA, cudaEventDisableTiming);
        cudaEventCreateWithFlags(&evB, cudaEventDisableTiming);
        cudaEventCreateWithFlags(&evJ, cudaEventDisableTiming);
    }

    init_kernel<<<(BATCH * N_HID + 255) / 256, 256>>>();
    {
        dim3 gT(N_HID / 32, N_OUT / 32);
        transpose_w2_kernel<<<gT, 256>>>(W2);
    }
    cudaEventRecord(evInit, 0);
    cudaStreamWaitEvent(sA, evInit, 0);
    cudaStreamWaitEvent(sB, evInit, 0);

    // gemm1 chunks on alternating streams; tails co-scheduled across streams.
    for (int c = 0; c < NCHUNK; c++) {
        cudaStream_t st = (c & 1) ? sB : sA;
        int m_base = c * ROWCHUNK;
        dim3 grid(N_HID / 128, ROWCHUNK / 128);   // (32, 10) = 320 blocks
        gemm1_half_kernel<<<grid, 256, 0, st>>>(x, W1, b1, m_base, 0);
        gemm1_half_kernel<<<grid, 256, 0, st>>>(x, W1, b1, m_base, 1);
        cudaEventRecord(evS[c], st);
    }
    cudaEventRecord(evA, sA);
    cudaEventRecord(evB, sB);

    float* out_spk_base = out;
    float* out_mem_base = out + (size_t)T_STEPS * BATCH * N_OUT;

    // Step recurrence on s2, gated per chunk.
    for (int c = 0; c < NCHUNK; c++) {
        cudaStreamWaitEvent(s2, evS[c], 0);
        for (int t = c * TCHUNK; t < (c + 1) * TCHUNK; t++) {
            step_fused_kernel<<<BATCH, 256, 0, s2>>>(
                t, b2,
                out_spk_base + (size_t)t * BATCH * N_OUT,
                out_mem_base + (size_t)t * BATCH * N_OUT);
        }
    }
    cudaEventRecord(evJ, s2);

    // Join everything back to stream 0.
    cudaStreamWaitEvent(0, evA, 0);
    cudaStreamWaitEvent(0, evB, 0);
    cudaStreamWaitEvent(0, evJ, 0);
}